// round 15
// baseline (speedup 1.0000x reference)
#include <cuda_runtime.h>
#include <cuda_fp16.h>
#include <cstdint>

// ---------------------------------------------------------------------------
// DecoderLayer: B=4, T=S=1024, D=1024, H=16, hd=64, F=4096, fp32 in/out.
// out = concat( tgt_out [4,1024,1024], cross_attn_probs [4,16,1024,1024] )
// R11: revert BN=256 (1 CTA/SM hurt; R5 lesson) -> all GEMMs BN=128 2 CTA/SM
// with 3-stage single-sync pipeline + NSEG routing. Keep R10 flash wins:
// no-max softmax (exact) and K-only cross pass 1.
// ---------------------------------------------------------------------------

namespace {
constexpr int Bz = 4;
constexpr int Tq = 1024;
constexpr int Dm = 1024;
constexpr int Hn = 16;
constexpr int Hd = 64;
constexpr int Fd = 4096;
constexpr int Mtok = Bz * Tq;
}

// ---- scratch (allocation-free device globals) ----
__device__ __half g_hA[Mtok * Dm];
__device__ __half g_hE[Mtok * Dm];
__device__ __half g_hQ[Mtok * Dm];
__device__ __half g_hK[Mtok * Dm];
__device__ __half g_hV[Mtok * Dm];
__device__ __half g_hVT[Mtok * Dm];
__device__ __half g_hT[Mtok * Dm];
__device__ __half g_hX[Mtok * Dm];
__device__ __half g_hFF[(size_t)Mtok * Fd];
__device__ __half g_hWqkv[(size_t)3 * Dm * Dm];
__device__ __half g_hWckv[(size_t)2 * Dm * Dm];
__device__ __half g_hWso[Dm * Dm], g_hWcq[Dm * Dm], g_hWco[Dm * Dm];
__device__ __half g_hW1[(size_t)Fd * Dm], g_hW2[(size_t)Dm * Fd];
__device__ float g_Bqkv[3 * Dm];
__device__ float g_Bckv[2 * Dm];
__device__ float g_F0[Mtok * Dm];
__device__ float g_X1[Mtok * Dm];
__device__ float g_X2[Mtok * Dm];

// ---------------------------------------------------------------------------
// helpers
// ---------------------------------------------------------------------------
__device__ __forceinline__ uint32_t s2u(const void* p) {
    uint32_t a;
    asm("{ .reg .u64 t; cvta.to.shared.u64 t, %1; cvt.u32.u64 %0, t; }"
        : "=r"(a) : "l"(p));
    return a;
}
__device__ __forceinline__ void cpa16(uint32_t dst, const void* src) {
    asm volatile("cp.async.cg.shared.global [%0], [%1], 16;" :: "r"(dst), "l"(src));
}
#define CP_COMMIT() asm volatile("cp.async.commit_group;" ::: "memory")
#define CP_WAIT(n)  asm volatile("cp.async.wait_group %0;" :: "n"(n) : "memory")

__device__ __forceinline__ uint32_t swz(uint32_t off) {   // 128B rows
    return off ^ ((off >> 3) & 0x70);
}
__device__ __forceinline__ uint32_t swzV(uint32_t off) {  // 256B rows
    return off ^ ((off >> 4) & 0x70);
}
__device__ __forceinline__ void ldsm4(unsigned& r0, unsigned& r1,
                                      unsigned& r2, unsigned& r3, uint32_t a) {
    asm volatile("ldmatrix.sync.aligned.m8n8.x4.shared.b16 {%0,%1,%2,%3}, [%4];"
                 : "=r"(r0), "=r"(r1), "=r"(r2), "=r"(r3) : "r"(a));
}
__device__ __forceinline__ void mma_f16(float c[4],
                                        unsigned a0, unsigned a1, unsigned a2, unsigned a3,
                                        unsigned b0, unsigned b1)
{
    asm volatile(
        "mma.sync.aligned.m16n8k16.row.col.f32.f16.f16.f32 "
        "{%0,%1,%2,%3}, {%4,%5,%6,%7}, {%8,%9}, {%0,%1,%2,%3};"
        : "+f"(c[0]), "+f"(c[1]), "+f"(c[2]), "+f"(c[3])
        : "r"(a0), "r"(a1), "r"(a2), "r"(a3), "r"(b0), "r"(b1));
}
__device__ __forceinline__ unsigned packh2(float a, float b) {
    __half2 t = __floats2half2_rn(a, b);
    return reinterpret_cast<unsigned&>(t);
}

// ---------------------------------------------------------------------------
// fp16 GEMM NT: C = A @ Bm^T (+bias)(+relu). BM=BN=128, BK=64.
// 3-stage cp.async, ONE sync per k-iter. 8 warps, warp tile 64x32, 2 CTAs/SM.
// NSEG>1: output cols are NSEG 1024-wide segments routed to C0/C1/C2.
// ---------------------------------------------------------------------------
template<int NSEG, bool OH>
__global__ void __launch_bounds__(256, 2)
gemm_h(const __half* __restrict__ A, int lda,
       const __half* __restrict__ Bm, int ldb,
       void* __restrict__ C0, void* __restrict__ C1, void* __restrict__ C2,
       int ldc, int Kdim, const float* __restrict__ bias, int relu)
{
    constexpr int MT = 4, NT = 4;
    constexpr int STG = 128 * 128;      // 16KB per stage per operand

    extern __shared__ unsigned char dsm[];
    const uint32_t sA = s2u(dsm);
    const uint32_t sB = sA + 3 * STG;

    const int tid  = threadIdx.x;
    const int warp = tid >> 5;
    const int lane = tid & 31;
    const int wm = warp & 1;
    const int wn = warp >> 1;
    const int row0 = blockIdx.y * 128;
    const int col0 = blockIdx.x * 128;
    const int lq = lane >> 2;
    const int lr = lane & 3;
    const int rA = lane & 15;
    const int cA = lane & 16;
    const int rB = (lane & 7) + ((lane & 16) >> 1);
    const int cB = (lane & 8) << 1;

    float acc[MT][NT][4];
#pragma unroll
    for (int i = 0; i < MT; i++)
#pragma unroll
        for (int j = 0; j < NT; j++)
#pragma unroll
            for (int v = 0; v < 4; v++) acc[i][j][v] = 0.f;

#define GISSUE(s, k0)                                                         \
    {                                                                         \
        _Pragma("unroll")                                                     \
        for (int i = 0; i < 4; i++) {                                         \
            int idx = tid + i * 256; int r = idx >> 3, ch = idx & 7;          \
            cpa16(sA + (s) * STG + swz(r * 128 + ch * 16),                    \
                  A + (long)(row0 + r) * lda + (k0) + ch * 8);                \
            cpa16(sB + (s) * STG + swz(r * 128 + ch * 16),                    \
                  Bm + (long)(col0 + r) * ldb + (k0) + ch * 8);               \
        }                                                                     \
        CP_COMMIT();                                                          \
    }

    const int nIter = Kdim / 64;
    GISSUE(0, 0);
    if (nIter > 1) GISSUE(1, 64);

    for (int it = 0; it < nIter; it++) {
        if (it + 1 < nIter) CP_WAIT(1); else CP_WAIT(0);
        __syncthreads();
        // safe: the barrier above retired all readers of buffer (it+2)%3
        if (it + 2 < nIter) GISSUE((it + 2) % 3, (it + 2) * 64);

        const uint32_t ab = sA + (it % 3) * STG;
        const uint32_t bb = sB + (it % 3) * STG;

#pragma unroll
        for (int ch = 0; ch < 4; ch++) {
            unsigned af[MT][4], bf[NT][2];
#pragma unroll
            for (int mi = 0; mi < MT; mi++)
                ldsm4(af[mi][0], af[mi][1], af[mi][2], af[mi][3],
                      ab + swz((wm * 64 + mi * 16 + rA) * 128 + cA + ch * 32));
#pragma unroll
            for (int nj = 0; nj < 2; nj++)
                ldsm4(bf[2 * nj][0], bf[2 * nj][1], bf[2 * nj + 1][0], bf[2 * nj + 1][1],
                      bb + swz((wn * 32 + nj * 16 + rB) * 128 + cB + ch * 32));
#pragma unroll
            for (int mi = 0; mi < MT; mi++)
#pragma unroll
                for (int ni = 0; ni < NT; ni++)
                    mma_f16(acc[mi][ni], af[mi][0], af[mi][1], af[mi][2], af[mi][3],
                            bf[ni][0], bf[ni][1]);
        }
    }
#undef GISSUE

    // epilogue: route to segment buffer
    void* Cd = C0;
    if (NSEG > 1) {
        int seg = col0 >> 10;
        Cd = (seg == 0) ? C0 : ((seg == 1) ? C1 : C2);
    }
#pragma unroll
    for (int mi = 0; mi < MT; mi++) {
#pragma unroll
        for (int ni = 0; ni < NT; ni++) {
            int r  = row0 + wm * 64 + mi * 16 + lq;
            int gc = col0 + wn * 32 + ni * 8 + lr * 2;
            int lc = (NSEG == 1) ? gc : (gc & 1023);
            float v00 = acc[mi][ni][0], v01 = acc[mi][ni][1];
            float v10 = acc[mi][ni][2], v11 = acc[mi][ni][3];
            if (bias) {
                float b0 = bias[gc], b1 = bias[gc + 1];
                v00 += b0; v01 += b1; v10 += b0; v11 += b1;
            }
            if (relu) {
                v00 = fmaxf(v00, 0.f); v01 = fmaxf(v01, 0.f);
                v10 = fmaxf(v10, 0.f); v11 = fmaxf(v11, 0.f);
            }
            if (OH) {
                __half* Ch = (__half*)Cd;
                *(__half2*)(Ch + (long)r * ldc + lc) = __floats2half2_rn(v00, v01);
                *(__half2*)(Ch + (long)(r + 8) * ldc + lc) = __floats2half2_rn(v10, v11);
            } else {
                float* Cf = (float*)Cd;
                *(float2*)(Cf + (long)r * ldc + lc) = make_float2(v00, v01);
                *(float2*)(Cf + (long)(r + 8) * ldc + lc) = make_float2(v10, v11);
            }
        }
    }
}

// ---------------------------------------------------------------------------
// Fused attention, no-max softmax (exact: shift-invariant; post-LN scores
// are O(+-6), far from exp overflow).
// MODE 0: self causal, single pass; O = (sum e V) / (sum e).
// MODE 1: cross. Pass1: K-only, row sums. Pass2: normalized fp32 probs ->
// Pout fused with PV.
// ---------------------------------------------------------------------------
template<int MODE>
__global__ void __launch_bounds__(256, 1)
flash_attn(const __half* __restrict__ Qp, const __half* __restrict__ Kp,
           const __half* __restrict__ VTp, __half* __restrict__ Op,
           float* __restrict__ Pout)
{
    constexpr int KBY = 128 * 128;
    constexpr int VBY = 64 * 256;
    extern __shared__ unsigned char dsm[];
    const uint32_t sQ = s2u(dsm);
    const uint32_t sK = sQ + 16384;
    const uint32_t sV = sK + 2 * KBY;

    const int qt = blockIdx.x;
    const int bh = blockIdx.y;
    const int b = bh >> 4, h = bh & 15;
    const long bTD = (long)Tq * Dm;
    const __half* Qh  = Qp  + (long)b * bTD + h * 64;
    const __half* Kh  = Kp  + (long)b * bTD + h * 64;
    const __half* Vh  = VTp + (long)b * bTD + (long)h * 64 * Tq;
    __half* Oh = Op + (long)b * bTD + h * 64;

    const int tid  = threadIdx.x;
    const int wid  = tid >> 5;
    const int lane = tid & 31;
    const int lq = lane >> 2;
    const int lr = lane & 3;
    const int rA = lane & 15;
    const int cA = lane & 16;
    const int rB = (lane & 7) + ((lane & 16) >> 1);
    const int cB = (lane & 8) << 1;

#define ISSUE_K(buf, kt)                                                      \
    {                                                                         \
        _Pragma("unroll")                                                     \
        for (int i = 0; i < 4; i++) {                                         \
            int idx = tid + i * 256;                                          \
            int r = idx >> 3, c = idx & 7;                                    \
            cpa16(sK + (buf) * KBY + swz(r * 128 + c * 16),                   \
                  Kh + (long)((kt) * 128 + r) * Dm + c * 8);                  \
        }                                                                     \
        CP_COMMIT();                                                          \
    }
#define ISSUE_KV(buf, kt)                                                     \
    {                                                                         \
        _Pragma("unroll")                                                     \
        for (int i = 0; i < 4; i++) {                                         \
            int idx = tid + i * 256;                                          \
            int r = idx >> 3, c = idx & 7;                                    \
            cpa16(sK + (buf) * KBY + swz(r * 128 + c * 16),                   \
                  Kh + (long)((kt) * 128 + r) * Dm + c * 8);                  \
        }                                                                     \
        _Pragma("unroll")                                                     \
        for (int i = 0; i < 4; i++) {                                         \
            int idx = tid + i * 256;                                          \
            int r = idx >> 4, c = idx & 15;                                   \
            cpa16(sV + (buf) * VBY + swzV(r * 256 + c * 16),                  \
                  Vh + (long)r * Tq + (kt) * 128 + c * 8);                    \
        }                                                                     \
        CP_COMMIT();                                                          \
    }
#define QK_TILE(kb_)                                                          \
    _Pragma("unroll")                                                         \
    for (int i = 0; i < 16; i++) {                                            \
        sacc[i][0] = 0.f; sacc[i][1] = 0.f;                                   \
        sacc[i][2] = 0.f; sacc[i][3] = 0.f;                                   \
    }                                                                         \
    _Pragma("unroll")                                                         \
    for (int ch = 0; ch < 4; ch++) {                                          \
        _Pragma("unroll")                                                     \
        for (int nj = 0; nj < 8; nj++) {                                      \
            unsigned b00, b01, b10, b11;                                      \
            ldsm4(b00, b01, b10, b11,                                         \
                  kb_ + swz((nj * 16 + rB) * 128 + cB + ch * 32));            \
            mma_f16(sacc[2 * nj], aq[ch][0], aq[ch][1], aq[ch][2], aq[ch][3], \
                    b00, b01);                                                \
            mma_f16(sacc[2 * nj + 1], aq[ch][0], aq[ch][1], aq[ch][2],        \
                    aq[ch][3], b10, b11);                                     \
        }                                                                     \
    }
#define PV_TILE(vb_)                                                          \
    _Pragma("unroll")                                                         \
    for (int c2 = 0; c2 < 8; c2++) {                                          \
        unsigned a0 = pa[2 * c2][0], a1 = pa[2 * c2][1];                      \
        unsigned a2 = pa[2 * c2 + 1][0], a3 = pa[2 * c2 + 1][1];              \
        _Pragma("unroll")                                                     \
        for (int nj = 0; nj < 4; nj++) {                                      \
            unsigned v00, v01, v10, v11;                                      \
            ldsm4(v00, v01, v10, v11,                                         \
                  vb_ + swzV((nj * 16 + rB) * 256 + cB + c2 * 32));           \
            mma_f16(oacc[2 * nj], a0, a1, a2, a3, v00, v01);                  \
            mma_f16(oacc[2 * nj + 1], a0, a1, a2, a3, v10, v11);              \
        }                                                                     \
    }

    // Q tile (once)
#pragma unroll
    for (int i = 0; i < 4; i++) {
        int idx = tid + i * 256;
        int r = idx >> 3, c = idx & 7;
        cpa16(sQ + swz(r * 128 + c * 16), Qh + (long)(qt * 128 + r) * Dm + c * 8);
    }
    CP_COMMIT();
    if (MODE == 0) ISSUE_KV(0, 0) else ISSUE_K(0, 0)
    CP_WAIT(1);
    __syncthreads();

    unsigned aq[4][4];
#pragma unroll
    for (int ch = 0; ch < 4; ch++)
        ldsm4(aq[ch][0], aq[ch][1], aq[ch][2], aq[ch][3],
              sQ + swz((wid * 16 + rA) * 128 + cA + ch * 32));

    float l0 = 0.f, l1 = 0.f;
    float oacc[8][4];
#pragma unroll
    for (int i = 0; i < 8; i++)
#pragma unroll
        for (int v = 0; v < 4; v++) oacc[i][v] = 0.f;
    float sacc[16][4];
    float invl0 = 1.f, invl1 = 1.f;
    const int nkt = (MODE == 0) ? (qt + 1) : 8;

    if (MODE == 0) {
        for (int kt = 0; kt < nkt; kt++) {
            int buf = kt & 1;
            if (kt + 1 < nkt) { ISSUE_KV((kt + 1) & 1, kt + 1) CP_WAIT(1); }
            else CP_WAIT(0);
            __syncthreads();
            const uint32_t kb_ = sK + buf * KBY;
            const uint32_t vb_ = sV + buf * VBY;
            QK_TILE(kb_)
            unsigned pa[16][2];
#pragma unroll
            for (int ni = 0; ni < 16; ni++) {
                float s0 = sacc[ni][0] * 0.125f, s1 = sacc[ni][1] * 0.125f;
                float s2 = sacc[ni][2] * 0.125f, s3 = sacc[ni][3] * 0.125f;
                if (kt == qt) {
                    int cl = ni * 8 + lr * 2;
                    int rl = wid * 16 + lq;
                    if (cl > rl)         s0 = -1e30f;
                    if (cl + 1 > rl)     s1 = -1e30f;
                    if (cl > rl + 8)     s2 = -1e30f;
                    if (cl + 1 > rl + 8) s3 = -1e30f;
                }
                float e0 = __expf(s0), e1 = __expf(s1);
                float e2 = __expf(s2), e3 = __expf(s3);
                l0 += e0 + e1; l1 += e2 + e3;
                pa[ni][0] = packh2(e0, e1);
                pa[ni][1] = packh2(e2, e3);
            }
            PV_TILE(vb_)
            __syncthreads();
        }
        l0 += __shfl_xor_sync(0xffffffffu, l0, 1);
        l0 += __shfl_xor_sync(0xffffffffu, l0, 2);
        l1 += __shfl_xor_sync(0xffffffffu, l1, 1);
        l1 += __shfl_xor_sync(0xffffffffu, l1, 2);
        invl0 = 1.f / l0;
        invl1 = 1.f / l1;
    } else {
        for (int kt = 0; kt < 8; kt++) {
            int buf = kt & 1;
            if (kt + 1 < 8) { ISSUE_K((kt + 1) & 1, kt + 1) CP_WAIT(1); }
            else CP_WAIT(0);
            __syncthreads();
            const uint32_t kb_ = sK + buf * KBY;
            QK_TILE(kb_)
#pragma unroll
            for (int ni = 0; ni < 16; ni++) {
                l0 += __expf(sacc[ni][0] * 0.125f) + __expf(sacc[ni][1] * 0.125f);
                l1 += __expf(sacc[ni][2] * 0.125f) + __expf(sacc[ni][3] * 0.125f);
            }
            __syncthreads();
        }
        l0 += __shfl_xor_sync(0xffffffffu, l0, 1);
        l0 += __shfl_xor_sync(0xffffffffu, l0, 2);
        l1 += __shfl_xor_sync(0xffffffffu, l1, 1);
        l1 += __shfl_xor_sync(0xffffffffu, l1, 2);
        invl0 = 1.f / l0;
        invl1 = 1.f / l1;
        ISSUE_KV(0, 0)
        for (int kt = 0; kt < 8; kt++) {
            int buf = kt & 1;
            if (kt + 1 < 8) { ISSUE_KV((kt + 1) & 1, kt + 1) CP_WAIT(1); }
            else CP_WAIT(0);
            __syncthreads();
            const uint32_t kb_ = sK + buf * KBY;
            const uint32_t vb_ = sV + buf * VBY;
            QK_TILE(kb_)
            unsigned pa[16][2];
#pragma unroll
            for (int ni = 0; ni < 16; ni++) {
                float e0 = __expf(sacc[ni][0] * 0.125f) * invl0;
                float e1 = __expf(sacc[ni][1] * 0.125f) * invl0;
                float e2 = __expf(sacc[ni][2] * 0.125f) * invl1;
                float e3 = __expf(sacc[ni][3] * 0.125f) * invl1;
                int row = qt * 128 + wid * 16 + lq;
                int col = kt * 128 + ni * 8 + lr * 2;
                float* pr = Pout + (long)bh * Tq * Tq;
                *(float2*)(pr + (long)row * Tq + col) = make_float2(e0, e1);
                *(float2*)(pr + (long)(row + 8) * Tq + col) = make_float2(e2, e3);
                pa[ni][0] = packh2(e0, e1);
                pa[ni][1] = packh2(e2, e3);
            }
            PV_TILE(vb_)
            __syncthreads();
        }
    }
#undef QK_TILE
#undef PV_TILE
#undef ISSUE_K
#undef ISSUE_KV

    const int row = qt * 128 + wid * 16 + lq;
#pragma unroll
    for (int no = 0; no < 8; no++) {
        int col = no * 8 + lr * 2;
        float v0 = oacc[no][0], v1 = oacc[no][1];
        float v2 = oacc[no][2], v3 = oacc[no][3];
        if (MODE == 0) { v0 *= invl0; v1 *= invl0; v2 *= invl1; v3 *= invl1; }
        *(__half2*)(Oh + (long)row * Dm + col) = __floats2half2_rn(v0, v1);
        *(__half2*)(Oh + (long)(row + 8) * Dm + col) = __floats2half2_rn(v2, v3);
    }
}

// ---------------------------------------------------------------------------
// Batched float->half converts + bias packer.
// ---------------------------------------------------------------------------
struct CvtN { const float* s[12]; __half* d[12]; int n4[12]; };

__global__ void __launch_bounds__(256)
f2hN(CvtN p)
{
    int w = blockIdx.y;
    int i = blockIdx.x * 256 + threadIdx.x;
    if (i < p.n4[w]) {
        float4 v = ((const float4*)p.s[w])[i];
        ((__half2*)p.d[w])[2 * i + 0] = __floats2half2_rn(v.x, v.y);
        ((__half2*)p.d[w])[2 * i + 1] = __floats2half2_rn(v.z, v.w);
    }
}

__global__ void __launch_bounds__(256)
pack_bias(const float* bq, const float* bk, const float* bv,
          const float* cbk, const float* cbv,
          float* Bqkv, float* Bckv)
{
    int i = blockIdx.x * 256 + threadIdx.x;
    if (i < 1024)       Bqkv[i] = bq[i];
    else if (i < 2048)  Bqkv[i] = bk[i - 1024];
    else if (i < 3072)  Bqkv[i] = bv[i - 2048];
    else if (i < 4096)  Bckv[i - 3072] = cbk[i - 3072];
    else if (i < 5120)  Bckv[i - 3072] = cbv[i - 4096];
}

// ---------------------------------------------------------------------------
// Transpose each head of half V: [T][64] -> VT [64][T], per (b,h).
// ---------------------------------------------------------------------------
__global__ void __launch_bounds__(256)
transpose_vh(const __half* __restrict__ V, __half* __restrict__ VT)
{
    __shared__ __half sm[64][68];
    int bh = blockIdx.y;
    int b = bh >> 4, h = bh & 15;
    int t0 = blockIdx.x * 64;
    const __half* src = V + (long)b * (Tq * Dm) + h * 64;
    __half* dst = VT + (long)b * (Tq * Dm) + (long)h * 64 * Tq;
    int tid = threadIdx.x;

#pragma unroll
    for (int i = 0; i < 4; i++) {
        int idx = tid + i * 256;
        int r = idx >> 4, c4 = (idx & 15) * 4;
        uint2 v = *(const uint2*)(src + (long)(t0 + r) * Dm + c4);
        *(uint2*)&sm[r][c4] = v;
    }
    __syncthreads();
#pragma unroll
    for (int i = 0; i < 4; i++) {
        int idx = tid + i * 256;
        int d = idx >> 4, t4 = (idx & 15) * 4;
        __half2 p0 = __halves2half2(sm[t4 + 0][d], sm[t4 + 1][d]);
        __half2 p1 = __halves2half2(sm[t4 + 2][d], sm[t4 + 3][d]);
        __half* dp = dst + (long)d * Tq + t0 + t4;
        *(__half2*)(dp + 0) = p0;
        *(__half2*)(dp + 2) = p1;
    }
}

// ---------------------------------------------------------------------------
// y = LayerNorm(a + r) * g + be; optional half copy yh.
// ---------------------------------------------------------------------------
__global__ void __launch_bounds__(256)
add_ln(const float* __restrict__ a, const float* __restrict__ r,
       const float* __restrict__ g, const float* __restrict__ be,
       float* __restrict__ y, __half* __restrict__ yh)
{
    const long off = (long)blockIdx.x * 1024;
    const int tid = threadIdx.x;
    const int w = tid >> 5, l = tid & 31;
    __shared__ float r1[8], r2[8];

    float4 xa = reinterpret_cast<const float4*>(a + off)[tid];
    float4 xr = reinterpret_cast<const float4*>(r + off)[tid];
    float4 x = make_float4(xa.x + xr.x, xa.y + xr.y, xa.z + xr.z, xa.w + xr.w);

    float s  = x.x + x.y + x.z + x.w;
    float ss = x.x * x.x + x.y * x.y + x.z * x.z + x.w * x.w;
#pragma unroll
    for (int o = 16; o > 0; o >>= 1) {
        s  += __shfl_xor_sync(0xffffffffu, s, o);
        ss += __shfl_xor_sync(0xffffffffu, ss, o);
    }
    if (l == 0) { r1[w] = s; r2[w] = ss; }
    __syncthreads();
    if (tid == 0) {
        float ts = 0.f, tss = 0.f;
#pragma unroll
        for (int i = 0; i < 8; i++) { ts += r1[i]; tss += r2[i]; }
        r1[0] = ts; r2[0] = tss;
    }
    __syncthreads();
    float mu   = r1[0] * (1.0f / 1024.0f);
    float var  = r2[0] * (1.0f / 1024.0f) - mu * mu;
    float rstd = rsqrtf(var + 1e-5f);

    float4 gg = reinterpret_cast<const float4*>(g)[tid];
    float4 bb = reinterpret_cast<const float4*>(be)[tid];
    float4 o;
    o.x = (x.x - mu) * rstd * gg.x + bb.x;
    o.y = (x.y - mu) * rstd * gg.y + bb.y;
    o.z = (x.z - mu) * rstd * gg.z + bb.z;
    o.w = (x.w - mu) * rstd * gg.w + bb.w;
    reinterpret_cast<float4*>(y + off)[tid] = o;
    if (yh) {
        *(__half2*)(yh + off + tid * 4 + 0) = __floats2half2_rn(o.x, o.y);
        *(__half2*)(yh + off + tid * 4 + 2) = __floats2half2_rn(o.z, o.w);
    }
}

// ---------------------------------------------------------------------------
// Host orchestration
// ---------------------------------------------------------------------------
static constexpr int GEMM_SMEM  = 3 * (128 * 128 + 128 * 128);  // 98304
static constexpr int FLASH_SMEM = 16384 + 2 * (128 * 128) + 2 * (64 * 256);

template<int NSEG, bool OH>
static void gx(const __half* A, int lda, const __half* Bm, int ldb,
               void* C0, void* C1, void* C2, int ldc,
               int M, int N, int K, const float* bias, int relu)
{
    dim3 grid(N / 128, M / 128, 1);
    gemm_h<NSEG, OH><<<grid, 256, GEMM_SMEM>>>(A, lda, Bm, ldb, C0, C1, C2,
                                               ldc, K, bias, relu);
}

extern "C" void kernel_launch(void* const* d_in, const int* in_sizes, int n_in,
                              void* d_out, int out_size)
{
    cudaFuncSetAttribute(gemm_h<1, true>,  cudaFuncAttributeMaxDynamicSharedMemorySize, GEMM_SMEM);
    cudaFuncSetAttribute(gemm_h<1, false>, cudaFuncAttributeMaxDynamicSharedMemorySize, GEMM_SMEM);
    cudaFuncSetAttribute(gemm_h<2, true>,  cudaFuncAttributeMaxDynamicSharedMemorySize, GEMM_SMEM);
    cudaFuncSetAttribute(gemm_h<3, true>,  cudaFuncAttributeMaxDynamicSharedMemorySize, GEMM_SMEM);
    cudaFuncSetAttribute(flash_attn<0>, cudaFuncAttributeMaxDynamicSharedMemorySize, FLASH_SMEM);
    cudaFuncSetAttribute(flash_attn<1>, cudaFuncAttributeMaxDynamicSharedMemorySize, FLASH_SMEM);

    const float* tgt   = (const float*)d_in[0];
    const float* enc   = (const float*)d_in[1];
    const float* sa_wq = (const float*)d_in[4];
    const float* sa_bq = (const float*)d_in[5];
    const float* sa_wk = (const float*)d_in[6];
    const float* sa_bk = (const float*)d_in[7];
    const float* sa_wv = (const float*)d_in[8];
    const float* sa_bv = (const float*)d_in[9];
    const float* sa_wo = (const float*)d_in[10];
    const float* sa_bo = (const float*)d_in[11];
    const float* ca_wq = (const float*)d_in[12];
    const float* ca_bq = (const float*)d_in[13];
    const float* ca_wk = (const float*)d_in[14];
    const float* ca_bk = (const float*)d_in[15];
    const float* ca_wv = (const float*)d_in[16];
    const float* ca_bv = (const float*)d_in[17];
    const float* ca_wo = (const float*)d_in[18];
    const float* ca_bo = (const float*)d_in[19];
    const float* ff_w1 = (const float*)d_in[20];
    const float* ff_b1 = (const float*)d_in[21];
    const float* ff_w2 = (const float*)d_in[22];
    const float* ff_b2 = (const float*)d_in[23];
    const float* ln1_g = (const float*)d_in[24];
    const float* ln1_b = (const float*)d_in[25];
    const float* ln2_g = (const float*)d_in[26];
    const float* ln2_b = (const float*)d_in[27];
    const float* ln3_g = (const float*)d_in[28];
    const float* ln3_b = (const float*)d_in[29];

    float* out_tgt  = (float*)d_out;
    float* out_attn = (float*)d_out + (long)Mtok * Dm;

    __half *hA, *hE, *hQ, *hK, *hV, *hVT, *hT, *hX, *hFF;
    __half *hWqkv, *hWckv, *hWso, *hWcq, *hWco, *hW1, *hW2;
    float *Bqkv, *Bckv, *F0, *X1, *X2;
    cudaGetSymbolAddress((void**)&hA, g_hA);
    cudaGetSymbolAddress((void**)&hE, g_hE);
    cudaGetSymbolAddress((void**)&hQ, g_hQ);
    cudaGetSymbolAddress((void**)&hK, g_hK);
    cudaGetSymbolAddress((void**)&hV, g_hV);
    cudaGetSymbolAddress((void**)&hVT, g_hVT);
    cudaGetSymbolAddress((void**)&hT, g_hT);
    cudaGetSymbolAddress((void**)&hX, g_hX);
    cudaGetSymbolAddress((void**)&hFF, g_hFF);
    cudaGetSymbolAddress((void**)&hWqkv, g_hWqkv);
    cudaGetSymbolAddress((void**)&hWckv, g_hWckv);
    cudaGetSymbolAddress((void**)&hWso, g_hWso);
    cudaGetSymbolAddress((void**)&hWcq, g_hWcq);
    cudaGetSymbolAddress((void**)&hWco, g_hWco);
    cudaGetSymbolAddress((void**)&hW1, g_hW1);
    cudaGetSymbolAddress((void**)&hW2, g_hW2);
    cudaGetSymbolAddress((void**)&Bqkv, g_Bqkv);
    cudaGetSymbolAddress((void**)&Bckv, g_Bckv);
    cudaGetSymbolAddress((void**)&F0, g_F0);
    cudaGetSymbolAddress((void**)&X1, g_X1);
    cudaGetSymbolAddress((void**)&X2, g_X2);

    const int DDe = Dm * Dm;
    const int nbh = Bz * Hn;
    dim3 tgrid(Tq / 64, nbh);
    dim3 fgrid(Tq / 128, nbh);

    // ---- converts: one batched kernel (12 slices) + bias pack ----
    {
        CvtN p;
        int td = Mtok * Dm / 4;
        int wd = DDe / 4;
        p.s[0] = tgt;    p.d[0] = hA;              p.n4[0] = td;
        p.s[1] = enc;    p.d[1] = hE;              p.n4[1] = td;
        p.s[2] = sa_wq;  p.d[2] = hWqkv;           p.n4[2] = wd;
        p.s[3] = sa_wk;  p.d[3] = hWqkv + DDe;     p.n4[3] = wd;
        p.s[4] = sa_wv;  p.d[4] = hWqkv + 2 * DDe; p.n4[4] = wd;
        p.s[5] = sa_wo;  p.d[5] = hWso;            p.n4[5] = wd;
        p.s[6] = ca_wq;  p.d[6] = hWcq;            p.n4[6] = wd;
        p.s[7] = ca_wk;  p.d[7] = hWckv;           p.n4[7] = wd;
        p.s[8] = ca_wv;  p.d[8] = hWckv + DDe;     p.n4[8] = wd;
        p.s[9] = ca_wo;  p.d[9] = hWco;            p.n4[9] = wd;
        p.s[10] = ff_w1; p.d[10] = hW1;            p.n4[10] = td;
        p.s[11] = ff_w2; p.d[11] = hW2;            p.n4[11] = td;
        dim3 cgrid((td + 255) / 256, 12);
        f2hN<<<cgrid, 256>>>(p);
        pack_bias<<<20, 256>>>(sa_bq, sa_bk, sa_bv, ca_bk, ca_bv, Bqkv, Bckv);
    }

    // ---- self-attention ----
    gx<3, true>(hA, Dm, hWqkv, Dm, hQ, hK, hV, Dm, Mtok, 3 * Dm, Dm, Bqkv, 0);
    transpose_vh<<<tgrid, 256>>>(hV, hVT);
    flash_attn<0><<<fgrid, 256, FLASH_SMEM>>>(hQ, hK, hVT, hT, nullptr);
    gx<1, false>(hT, Dm, hWso, Dm, F0, nullptr, nullptr, Dm, Mtok, Dm, Dm, sa_bo, 0);
    add_ln<<<Mtok, 256>>>(F0, tgt, ln1_g, ln1_b, X1, hX);

    // ---- cross-attention (probs fused straight into d_out) ----
    gx<1, true>(hX, Dm, hWcq, Dm, hQ, nullptr, nullptr, Dm, Mtok, Dm, Dm, ca_bq, 0);
    gx<2, true>(hE, Dm, hWckv, Dm, hK, hV, nullptr, Dm, Mtok, 2 * Dm, Dm, Bckv, 0);
    transpose_vh<<<tgrid, 256>>>(hV, hVT);
    flash_attn<1><<<fgrid, 256, FLASH_SMEM>>>(hQ, hK, hVT, hT, out_attn);
    gx<1, false>(hT, Dm, hWco, Dm, F0, nullptr, nullptr, Dm, Mtok, Dm, Dm, ca_bo, 0);
    add_ln<<<Mtok, 256>>>(F0, X1, ln2_g, ln2_b, X2, hX);

    // ---- feed-forward ----
    gx<1, true>(hX, Dm, hW1, Dm, hFF, nullptr, nullptr, Fd, Mtok, Fd, Dm, ff_b1, 1);
    gx<1, false>(hFF, Fd, hW2, Fd, F0, nullptr, nullptr, Dm, Mtok, Dm, Fd, ff_b2, 0);
    add_ln<<<Mtok, 256>>>(F0, X2, ln3_g, ln3_b, out_tgt, nullptr);
}

// round 17
// speedup vs baseline: 1.5100x; 1.5100x over previous
#include <cuda_runtime.h>
#include <cuda_fp16.h>
#include <cstdint>

// ---------------------------------------------------------------------------
// DecoderLayer: B=4, T=S=1024, D=1024, H=16, hd=64, F=4096, fp32 in/out.
// out = concat( tgt_out [4,1024,1024], cross_attn_probs [4,16,1024,1024] )
// R12: GEMM = R9's proven 2-stage BK=64 two-sync 64KB kernel (best measured).
// Flash keeps no-max softmax + K-only cross pass1 (R10/R11 wins).
// ---------------------------------------------------------------------------

namespace {
constexpr int Bz = 4;
constexpr int Tq = 1024;
constexpr int Dm = 1024;
constexpr int Hn = 16;
constexpr int Hd = 64;
constexpr int Fd = 4096;
constexpr int Mtok = Bz * Tq;
}

// ---- scratch (allocation-free device globals) ----
__device__ __half g_hA[Mtok * Dm];
__device__ __half g_hE[Mtok * Dm];
__device__ __half g_hQ[Mtok * Dm];
__device__ __half g_hK[Mtok * Dm];
__device__ __half g_hV[Mtok * Dm];
__device__ __half g_hVT[Mtok * Dm];
__device__ __half g_hT[Mtok * Dm];
__device__ __half g_hX[Mtok * Dm];
__device__ __half g_hFF[(size_t)Mtok * Fd];
__device__ __half g_hWqkv[(size_t)3 * Dm * Dm];
__device__ __half g_hWckv[(size_t)2 * Dm * Dm];
__device__ __half g_hWso[Dm * Dm], g_hWcq[Dm * Dm], g_hWco[Dm * Dm];
__device__ __half g_hW1[(size_t)Fd * Dm], g_hW2[(size_t)Dm * Fd];
__device__ float g_Bqkv[3 * Dm];
__device__ float g_Bckv[2 * Dm];
__device__ float g_F0[Mtok * Dm];
__device__ float g_X1[Mtok * Dm];
__device__ float g_X2[Mtok * Dm];

// ---------------------------------------------------------------------------
// helpers
// ---------------------------------------------------------------------------
__device__ __forceinline__ uint32_t s2u(const void* p) {
    uint32_t a;
    asm("{ .reg .u64 t; cvta.to.shared.u64 t, %1; cvt.u32.u64 %0, t; }"
        : "=r"(a) : "l"(p));
    return a;
}
__device__ __forceinline__ void cpa16(uint32_t dst, const void* src) {
    asm volatile("cp.async.cg.shared.global [%0], [%1], 16;" :: "r"(dst), "l"(src));
}
#define CP_COMMIT() asm volatile("cp.async.commit_group;" ::: "memory")
#define CP_WAIT(n)  asm volatile("cp.async.wait_group %0;" :: "n"(n) : "memory")

__device__ __forceinline__ uint32_t swz(uint32_t off) {   // 128B rows
    return off ^ ((off >> 3) & 0x70);
}
__device__ __forceinline__ uint32_t swzV(uint32_t off) {  // 256B rows
    return off ^ ((off >> 4) & 0x70);
}
__device__ __forceinline__ void ldsm4(unsigned& r0, unsigned& r1,
                                      unsigned& r2, unsigned& r3, uint32_t a) {
    asm volatile("ldmatrix.sync.aligned.m8n8.x4.shared.b16 {%0,%1,%2,%3}, [%4];"
                 : "=r"(r0), "=r"(r1), "=r"(r2), "=r"(r3) : "r"(a));
}
__device__ __forceinline__ void mma_f16(float c[4],
                                        unsigned a0, unsigned a1, unsigned a2, unsigned a3,
                                        unsigned b0, unsigned b1)
{
    asm volatile(
        "mma.sync.aligned.m16n8k16.row.col.f32.f16.f16.f32 "
        "{%0,%1,%2,%3}, {%4,%5,%6,%7}, {%8,%9}, {%0,%1,%2,%3};"
        : "+f"(c[0]), "+f"(c[1]), "+f"(c[2]), "+f"(c[3])
        : "r"(a0), "r"(a1), "r"(a2), "r"(a3), "r"(b0), "r"(b1));
}
__device__ __forceinline__ unsigned packh2(float a, float b) {
    __half2 t = __floats2half2_rn(a, b);
    return reinterpret_cast<unsigned&>(t);
}

// ---------------------------------------------------------------------------
// fp16 GEMM NT (R9-proven): C = A @ Bm^T (+bias)(+relu). BM=BN=128, BK=64,
// 2-stage cp.async, two syncs per k-iter, 64KB smem, 2 CTAs/SM.
// NSEG>1: output cols are NSEG 1024-wide segments routed to C0/C1/C2.
// ---------------------------------------------------------------------------
template<int NSEG, bool OH>
__global__ void __launch_bounds__(256, 2)
gemm_h(const __half* __restrict__ A, int lda,
       const __half* __restrict__ Bm, int ldb,
       void* __restrict__ C0, void* __restrict__ C1, void* __restrict__ C2,
       int ldc, int Kdim, const float* __restrict__ bias, int relu)
{
    constexpr int MT = 4, NT = 4;
    constexpr int ABY = 128 * 128;      // 16KB per stage per operand

    extern __shared__ unsigned char dsm[];
    const uint32_t sA = s2u(dsm);
    const uint32_t sB = sA + 2 * ABY;

    const int tid  = threadIdx.x;
    const int warp = tid >> 5;
    const int lane = tid & 31;
    const int wm = warp & 1;
    const int wn = warp >> 1;
    const int row0 = blockIdx.y * 128;
    const int col0 = blockIdx.x * 128;
    const int lq = lane >> 2;
    const int lr = lane & 3;
    const int rA = lane & 15;
    const int cA = lane & 16;
    const int rB = (lane & 7) + ((lane & 16) >> 1);
    const int cB = (lane & 8) << 1;

    float acc[MT][NT][4];
#pragma unroll
    for (int i = 0; i < MT; i++)
#pragma unroll
        for (int j = 0; j < NT; j++)
#pragma unroll
            for (int v = 0; v < 4; v++) acc[i][j][v] = 0.f;

#define GISSUE(s, k0)                                                         \
    {                                                                         \
        _Pragma("unroll")                                                     \
        for (int i = 0; i < 4; i++) {                                         \
            int idx = tid + i * 256; int r = idx >> 3, ch = idx & 7;          \
            cpa16(sA + (s) * ABY + swz(r * 128 + ch * 16),                    \
                  A + (long)(row0 + r) * lda + (k0) + ch * 8);                \
            cpa16(sB + (s) * ABY + swz(r * 128 + ch * 16),                    \
                  Bm + (long)(col0 + r) * ldb + (k0) + ch * 8);               \
        }                                                                     \
        CP_COMMIT();                                                          \
    }

    const int nIter = Kdim / 64;
    GISSUE(0, 0);
    if (nIter > 1) GISSUE(1, 64);

    for (int it = 0; it < nIter; it++) {
        if (it + 1 < nIter) CP_WAIT(1); else CP_WAIT(0);
        __syncthreads();

        const uint32_t ab = sA + (it & 1) * ABY;
        const uint32_t bb = sB + (it & 1) * ABY;

#pragma unroll
        for (int ch = 0; ch < 4; ch++) {
            unsigned af[MT][4], bf[NT][2];
#pragma unroll
            for (int mi = 0; mi < MT; mi++)
                ldsm4(af[mi][0], af[mi][1], af[mi][2], af[mi][3],
                      ab + swz((wm * 64 + mi * 16 + rA) * 128 + cA + ch * 32));
#pragma unroll
            for (int nj = 0; nj < 2; nj++)
                ldsm4(bf[2 * nj][0], bf[2 * nj][1], bf[2 * nj + 1][0], bf[2 * nj + 1][1],
                      bb + swz((wn * 32 + nj * 16 + rB) * 128 + cB + ch * 32));
#pragma unroll
            for (int mi = 0; mi < MT; mi++)
#pragma unroll
                for (int ni = 0; ni < NT; ni++)
                    mma_f16(acc[mi][ni], af[mi][0], af[mi][1], af[mi][2], af[mi][3],
                            bf[ni][0], bf[ni][1]);
        }
        __syncthreads();
        if (it + 2 < nIter) GISSUE(it & 1, (it + 2) * 64);
    }
#undef GISSUE

    // epilogue: route to segment buffer
    void* Cd = C0;
    if (NSEG > 1) {
        int seg = col0 >> 10;
        Cd = (seg == 0) ? C0 : ((seg == 1) ? C1 : C2);
    }
#pragma unroll
    for (int mi = 0; mi < MT; mi++) {
#pragma unroll
        for (int ni = 0; ni < NT; ni++) {
            int r  = row0 + wm * 64 + mi * 16 + lq;
            int gc = col0 + wn * 32 + ni * 8 + lr * 2;
            int lc = (NSEG == 1) ? gc : (gc & 1023);
            float v00 = acc[mi][ni][0], v01 = acc[mi][ni][1];
            float v10 = acc[mi][ni][2], v11 = acc[mi][ni][3];
            if (bias) {
                float b0 = bias[gc], b1 = bias[gc + 1];
                v00 += b0; v01 += b1; v10 += b0; v11 += b1;
            }
            if (relu) {
                v00 = fmaxf(v00, 0.f); v01 = fmaxf(v01, 0.f);
                v10 = fmaxf(v10, 0.f); v11 = fmaxf(v11, 0.f);
            }
            if (OH) {
                __half* Ch = (__half*)Cd;
                *(__half2*)(Ch + (long)r * ldc + lc) = __floats2half2_rn(v00, v01);
                *(__half2*)(Ch + (long)(r + 8) * ldc + lc) = __floats2half2_rn(v10, v11);
            } else {
                float* Cf = (float*)Cd;
                *(float2*)(Cf + (long)r * ldc + lc) = make_float2(v00, v01);
                *(float2*)(Cf + (long)(r + 8) * ldc + lc) = make_float2(v10, v11);
            }
        }
    }
}

// ---------------------------------------------------------------------------
// Fused attention, no-max softmax (exact: shift-invariant; post-LN scores
// are O(+-6), far from exp overflow).
// MODE 0: self causal, single pass; O = (sum e V) / (sum e).
// MODE 1: cross. Pass1: K-only, row sums. Pass2: normalized fp32 probs ->
// Pout fused with PV.
// ---------------------------------------------------------------------------
template<int MODE>
__global__ void __launch_bounds__(256, 1)
flash_attn(const __half* __restrict__ Qp, const __half* __restrict__ Kp,
           const __half* __restrict__ VTp, __half* __restrict__ Op,
           float* __restrict__ Pout)
{
    constexpr int KBY = 128 * 128;
    constexpr int VBY = 64 * 256;
    extern __shared__ unsigned char dsm[];
    const uint32_t sQ = s2u(dsm);
    const uint32_t sK = sQ + 16384;
    const uint32_t sV = sK + 2 * KBY;

    const int qt = blockIdx.x;
    const int bh = blockIdx.y;
    const int b = bh >> 4, h = bh & 15;
    const long bTD = (long)Tq * Dm;
    const __half* Qh  = Qp  + (long)b * bTD + h * 64;
    const __half* Kh  = Kp  + (long)b * bTD + h * 64;
    const __half* Vh  = VTp + (long)b * bTD + (long)h * 64 * Tq;
    __half* Oh = Op + (long)b * bTD + h * 64;

    const int tid  = threadIdx.x;
    const int wid  = tid >> 5;
    const int lane = tid & 31;
    const int lq = lane >> 2;
    const int lr = lane & 3;
    const int rA = lane & 15;
    const int cA = lane & 16;
    const int rB = (lane & 7) + ((lane & 16) >> 1);
    const int cB = (lane & 8) << 1;

#define ISSUE_K(buf, kt)                                                      \
    {                                                                         \
        _Pragma("unroll")                                                     \
        for (int i = 0; i < 4; i++) {                                         \
            int idx = tid + i * 256;                                          \
            int r = idx >> 3, c = idx & 7;                                    \
            cpa16(sK + (buf) * KBY + swz(r * 128 + c * 16),                   \
                  Kh + (long)((kt) * 128 + r) * Dm + c * 8);                  \
        }                                                                     \
        CP_COMMIT();                                                          \
    }
#define ISSUE_KV(buf, kt)                                                     \
    {                                                                         \
        _Pragma("unroll")                                                     \
        for (int i = 0; i < 4; i++) {                                         \
            int idx = tid + i * 256;                                          \
            int r = idx >> 3, c = idx & 7;                                    \
            cpa16(sK + (buf) * KBY + swz(r * 128 + c * 16),                   \
                  Kh + (long)((kt) * 128 + r) * Dm + c * 8);                  \
        }                                                                     \
        _Pragma("unroll")                                                     \
        for (int i = 0; i < 4; i++) {                                         \
            int idx = tid + i * 256;                                          \
            int r = idx >> 4, c = idx & 15;                                   \
            cpa16(sV + (buf) * VBY + swzV(r * 256 + c * 16),                  \
                  Vh + (long)r * Tq + (kt) * 128 + c * 8);                    \
        }                                                                     \
        CP_COMMIT();                                                          \
    }
#define QK_TILE(kb_)                                                          \
    _Pragma("unroll")                                                         \
    for (int i = 0; i < 16; i++) {                                            \
        sacc[i][0] = 0.f; sacc[i][1] = 0.f;                                   \
        sacc[i][2] = 0.f; sacc[i][3] = 0.f;                                   \
    }                                                                         \
    _Pragma("unroll")                                                         \
    for (int ch = 0; ch < 4; ch++) {                                          \
        _Pragma("unroll")                                                     \
        for (int nj = 0; nj < 8; nj++) {                                      \
            unsigned b00, b01, b10, b11;                                      \
            ldsm4(b00, b01, b10, b11,                                         \
                  kb_ + swz((nj * 16 + rB) * 128 + cB + ch * 32));            \
            mma_f16(sacc[2 * nj], aq[ch][0], aq[ch][1], aq[ch][2], aq[ch][3], \
                    b00, b01);                                                \
            mma_f16(sacc[2 * nj + 1], aq[ch][0], aq[ch][1], aq[ch][2],        \
                    aq[ch][3], b10, b11);                                     \
        }                                                                     \
    }
#define PV_TILE(vb_)                                                          \
    _Pragma("unroll")                                                         \
    for (int c2 = 0; c2 < 8; c2++) {                                          \
        unsigned a0 = pa[2 * c2][0], a1 = pa[2 * c2][1];                      \
        unsigned a2 = pa[2 * c2 + 1][0], a3 = pa[2 * c2 + 1][1];              \
        _Pragma("unroll")                                                     \
        for (int nj = 0; nj < 4; nj++) {                                      \
            unsigned v00, v01, v10, v11;                                      \
            ldsm4(v00, v01, v10, v11,                                         \
                  vb_ + swzV((nj * 16 + rB) * 256 + cB + c2 * 32));           \
            mma_f16(oacc[2 * nj], a0, a1, a2, a3, v00, v01);                  \
            mma_f16(oacc[2 * nj + 1], a0, a1, a2, a3, v10, v11);              \
        }                                                                     \
    }

    // Q tile (once)
#pragma unroll
    for (int i = 0; i < 4; i++) {
        int idx = tid + i * 256;
        int r = idx >> 3, c = idx & 7;
        cpa16(sQ + swz(r * 128 + c * 16), Qh + (long)(qt * 128 + r) * Dm + c * 8);
    }
    CP_COMMIT();
    if (MODE == 0) ISSUE_KV(0, 0) else ISSUE_K(0, 0)
    CP_WAIT(1);
    __syncthreads();

    unsigned aq[4][4];
#pragma unroll
    for (int ch = 0; ch < 4; ch++)
        ldsm4(aq[ch][0], aq[ch][1], aq[ch][2], aq[ch][3],
              sQ + swz((wid * 16 + rA) * 128 + cA + ch * 32));

    float l0 = 0.f, l1 = 0.f;
    float oacc[8][4];
#pragma unroll
    for (int i = 0; i < 8; i++)
#pragma unroll
        for (int v = 0; v < 4; v++) oacc[i][v] = 0.f;
    float sacc[16][4];
    float invl0 = 1.f, invl1 = 1.f;
    const int nkt = (MODE == 0) ? (qt + 1) : 8;

    if (MODE == 0) {
        for (int kt = 0; kt < nkt; kt++) {
            int buf = kt & 1;
            if (kt + 1 < nkt) { ISSUE_KV((kt + 1) & 1, kt + 1) CP_WAIT(1); }
            else CP_WAIT(0);
            __syncthreads();
            const uint32_t kb_ = sK + buf * KBY;
            const uint32_t vb_ = sV + buf * VBY;
            QK_TILE(kb_)
            unsigned pa[16][2];
#pragma unroll
            for (int ni = 0; ni < 16; ni++) {
                float s0 = sacc[ni][0] * 0.125f, s1 = sacc[ni][1] * 0.125f;
                float s2 = sacc[ni][2] * 0.125f, s3 = sacc[ni][3] * 0.125f;
                if (kt == qt) {
                    int cl = ni * 8 + lr * 2;
                    int rl = wid * 16 + lq;
                    if (cl > rl)         s0 = -1e30f;
                    if (cl + 1 > rl)     s1 = -1e30f;
                    if (cl > rl + 8)     s2 = -1e30f;
                    if (cl + 1 > rl + 8) s3 = -1e30f;
                }
                float e0 = __expf(s0), e1 = __expf(s1);
                float e2 = __expf(s2), e3 = __expf(s3);
                l0 += e0 + e1; l1 += e2 + e3;
                pa[ni][0] = packh2(e0, e1);
                pa[ni][1] = packh2(e2, e3);
            }
            PV_TILE(vb_)
            __syncthreads();
        }
        l0 += __shfl_xor_sync(0xffffffffu, l0, 1);
        l0 += __shfl_xor_sync(0xffffffffu, l0, 2);
        l1 += __shfl_xor_sync(0xffffffffu, l1, 1);
        l1 += __shfl_xor_sync(0xffffffffu, l1, 2);
        invl0 = 1.f / l0;
        invl1 = 1.f / l1;
    } else {
        for (int kt = 0; kt < 8; kt++) {
            int buf = kt & 1;
            if (kt + 1 < 8) { ISSUE_K((kt + 1) & 1, kt + 1) CP_WAIT(1); }
            else CP_WAIT(0);
            __syncthreads();
            const uint32_t kb_ = sK + buf * KBY;
            QK_TILE(kb_)
#pragma unroll
            for (int ni = 0; ni < 16; ni++) {
                l0 += __expf(sacc[ni][0] * 0.125f) + __expf(sacc[ni][1] * 0.125f);
                l1 += __expf(sacc[ni][2] * 0.125f) + __expf(sacc[ni][3] * 0.125f);
            }
            __syncthreads();
        }
        l0 += __shfl_xor_sync(0xffffffffu, l0, 1);
        l0 += __shfl_xor_sync(0xffffffffu, l0, 2);
        l1 += __shfl_xor_sync(0xffffffffu, l1, 1);
        l1 += __shfl_xor_sync(0xffffffffu, l1, 2);
        invl0 = 1.f / l0;
        invl1 = 1.f / l1;
        ISSUE_KV(0, 0)
        for (int kt = 0; kt < 8; kt++) {
            int buf = kt & 1;
            if (kt + 1 < 8) { ISSUE_KV((kt + 1) & 1, kt + 1) CP_WAIT(1); }
            else CP_WAIT(0);
            __syncthreads();
            const uint32_t kb_ = sK + buf * KBY;
            const uint32_t vb_ = sV + buf * VBY;
            QK_TILE(kb_)
            unsigned pa[16][2];
#pragma unroll
            for (int ni = 0; ni < 16; ni++) {
                float e0 = __expf(sacc[ni][0] * 0.125f) * invl0;
                float e1 = __expf(sacc[ni][1] * 0.125f) * invl0;
                float e2 = __expf(sacc[ni][2] * 0.125f) * invl1;
                float e3 = __expf(sacc[ni][3] * 0.125f) * invl1;
                int row = qt * 128 + wid * 16 + lq;
                int col = kt * 128 + ni * 8 + lr * 2;
                float* pr = Pout + (long)bh * Tq * Tq;
                *(float2*)(pr + (long)row * Tq + col) = make_float2(e0, e1);
                *(float2*)(pr + (long)(row + 8) * Tq + col) = make_float2(e2, e3);
                pa[ni][0] = packh2(e0, e1);
                pa[ni][1] = packh2(e2, e3);
            }
            PV_TILE(vb_)
            __syncthreads();
        }
    }
#undef QK_TILE
#undef PV_TILE
#undef ISSUE_K
#undef ISSUE_KV

    const int row = qt * 128 + wid * 16 + lq;
#pragma unroll
    for (int no = 0; no < 8; no++) {
        int col = no * 8 + lr * 2;
        float v0 = oacc[no][0], v1 = oacc[no][1];
        float v2 = oacc[no][2], v3 = oacc[no][3];
        if (MODE == 0) { v0 *= invl0; v1 *= invl0; v2 *= invl1; v3 *= invl1; }
        *(__half2*)(Oh + (long)row * Dm + col) = __floats2half2_rn(v0, v1);
        *(__half2*)(Oh + (long)(row + 8) * Dm + col) = __floats2half2_rn(v2, v3);
    }
}

// ---------------------------------------------------------------------------
// Batched float->half converts + bias packer.
// ---------------------------------------------------------------------------
struct CvtN { const float* s[12]; __half* d[12]; int n4[12]; };

__global__ void __launch_bounds__(256)
f2hN(CvtN p)
{
    int w = blockIdx.y;
    int i = blockIdx.x * 256 + threadIdx.x;
    if (i < p.n4[w]) {
        float4 v = ((const float4*)p.s[w])[i];
        ((__half2*)p.d[w])[2 * i + 0] = __floats2half2_rn(v.x, v.y);
        ((__half2*)p.d[w])[2 * i + 1] = __floats2half2_rn(v.z, v.w);
    }
}

__global__ void __launch_bounds__(256)
pack_bias(const float* bq, const float* bk, const float* bv,
          const float* cbk, const float* cbv,
          float* Bqkv, float* Bckv)
{
    int i = blockIdx.x * 256 + threadIdx.x;
    if (i < 1024)       Bqkv[i] = bq[i];
    else if (i < 2048)  Bqkv[i] = bk[i - 1024];
    else if (i < 3072)  Bqkv[i] = bv[i - 2048];
    else if (i < 4096)  Bckv[i - 3072] = cbk[i - 3072];
    else if (i < 5120)  Bckv[i - 3072] = cbv[i - 4096];
}

// ---------------------------------------------------------------------------
// Transpose each head of half V: [T][64] -> VT [64][T], per (b,h).
// ---------------------------------------------------------------------------
__global__ void __launch_bounds__(256)
transpose_vh(const __half* __restrict__ V, __half* __restrict__ VT)
{
    __shared__ __half sm[64][68];
    int bh = blockIdx.y;
    int b = bh >> 4, h = bh & 15;
    int t0 = blockIdx.x * 64;
    const __half* src = V + (long)b * (Tq * Dm) + h * 64;
    __half* dst = VT + (long)b * (Tq * Dm) + (long)h * 64 * Tq;
    int tid = threadIdx.x;

#pragma unroll
    for (int i = 0; i < 4; i++) {
        int idx = tid + i * 256;
        int r = idx >> 4, c4 = (idx & 15) * 4;
        uint2 v = *(const uint2*)(src + (long)(t0 + r) * Dm + c4);
        *(uint2*)&sm[r][c4] = v;
    }
    __syncthreads();
#pragma unroll
    for (int i = 0; i < 4; i++) {
        int idx = tid + i * 256;
        int d = idx >> 4, t4 = (idx & 15) * 4;
        __half2 p0 = __halves2half2(sm[t4 + 0][d], sm[t4 + 1][d]);
        __half2 p1 = __halves2half2(sm[t4 + 2][d], sm[t4 + 3][d]);
        __half* dp = dst + (long)d * Tq + t0 + t4;
        *(__half2*)(dp + 0) = p0;
        *(__half2*)(dp + 2) = p1;
    }
}

// ---------------------------------------------------------------------------
// y = LayerNorm(a + r) * g + be; optional half copy yh.
// ---------------------------------------------------------------------------
__global__ void __launch_bounds__(256)
add_ln(const float* __restrict__ a, const float* __restrict__ r,
       const float* __restrict__ g, const float* __restrict__ be,
       float* __restrict__ y, __half* __restrict__ yh)
{
    const long off = (long)blockIdx.x * 1024;
    const int tid = threadIdx.x;
    const int w = tid >> 5, l = tid & 31;
    __shared__ float r1[8], r2[8];

    float4 xa = reinterpret_cast<const float4*>(a + off)[tid];
    float4 xr = reinterpret_cast<const float4*>(r + off)[tid];
    float4 x = make_float4(xa.x + xr.x, xa.y + xr.y, xa.z + xr.z, xa.w + xr.w);

    float s  = x.x + x.y + x.z + x.w;
    float ss = x.x * x.x + x.y * x.y + x.z * x.z + x.w * x.w;
#pragma unroll
    for (int o = 16; o > 0; o >>= 1) {
        s  += __shfl_xor_sync(0xffffffffu, s, o);
        ss += __shfl_xor_sync(0xffffffffu, ss, o);
    }
    if (l == 0) { r1[w] = s; r2[w] = ss; }
    __syncthreads();
    if (tid == 0) {
        float ts = 0.f, tss = 0.f;
#pragma unroll
        for (int i = 0; i < 8; i++) { ts += r1[i]; tss += r2[i]; }
        r1[0] = ts; r2[0] = tss;
    }
    __syncthreads();
    float mu   = r1[0] * (1.0f / 1024.0f);
    float var  = r2[0] * (1.0f / 1024.0f) - mu * mu;
    float rstd = rsqrtf(var + 1e-5f);

    float4 gg = reinterpret_cast<const float4*>(g)[tid];
    float4 bb = reinterpret_cast<const float4*>(be)[tid];
    float4 o;
    o.x = (x.x - mu) * rstd * gg.x + bb.x;
    o.y = (x.y - mu) * rstd * gg.y + bb.y;
    o.z = (x.z - mu) * rstd * gg.z + bb.z;
    o.w = (x.w - mu) * rstd * gg.w + bb.w;
    reinterpret_cast<float4*>(y + off)[tid] = o;
    if (yh) {
        *(__half2*)(yh + off + tid * 4 + 0) = __floats2half2_rn(o.x, o.y);
        *(__half2*)(yh + off + tid * 4 + 2) = __floats2half2_rn(o.z, o.w);
    }
}

// ---------------------------------------------------------------------------
// Host orchestration
// ---------------------------------------------------------------------------
static constexpr int GEMM_SMEM  = 2 * (128 * 128 + 128 * 128);  // 65536
static constexpr int FLASH_SMEM = 16384 + 2 * (128 * 128) + 2 * (64 * 256);

template<int NSEG, bool OH>
static void gx(const __half* A, int lda, const __half* Bm, int ldb,
               void* C0, void* C1, void* C2, int ldc,
               int M, int N, int K, const float* bias, int relu)
{
    dim3 grid(N / 128, M / 128, 1);
    gemm_h<NSEG, OH><<<grid, 256, GEMM_SMEM>>>(A, lda, Bm, ldb, C0, C1, C2,
                                               ldc, K, bias, relu);
}

extern "C" void kernel_launch(void* const* d_in, const int* in_sizes, int n_in,
                              void* d_out, int out_size)
{
    cudaFuncSetAttribute(gemm_h<1, true>,  cudaFuncAttributeMaxDynamicSharedMemorySize, GEMM_SMEM);
    cudaFuncSetAttribute(gemm_h<1, false>, cudaFuncAttributeMaxDynamicSharedMemorySize, GEMM_SMEM);
    cudaFuncSetAttribute(gemm_h<2, true>,  cudaFuncAttributeMaxDynamicSharedMemorySize, GEMM_SMEM);
    cudaFuncSetAttribute(gemm_h<3, true>,  cudaFuncAttributeMaxDynamicSharedMemorySize, GEMM_SMEM);
    cudaFuncSetAttribute(flash_attn<0>, cudaFuncAttributeMaxDynamicSharedMemorySize, FLASH_SMEM);
    cudaFuncSetAttribute(flash_attn<1>, cudaFuncAttributeMaxDynamicSharedMemorySize, FLASH_SMEM);

    const float* tgt   = (const float*)d_in[0];
    const float* enc   = (const float*)d_in[1];
    const float* sa_wq = (const float*)d_in[4];
    const float* sa_bq = (const float*)d_in[5];
    const float* sa_wk = (const float*)d_in[6];
    const float* sa_bk = (const float*)d_in[7];
    const float* sa_wv = (const float*)d_in[8];
    const float* sa_bv = (const float*)d_in[9];
    const float* sa_wo = (const float*)d_in[10];
    const float* sa_bo = (const float*)d_in[11];
    const float* ca_wq = (const float*)d_in[12];
    const float* ca_bq = (const float*)d_in[13];
    const float* ca_wk = (const float*)d_in[14];
    const float* ca_bk = (const float*)d_in[15];
    const float* ca_wv = (const float*)d_in[16];
    const float* ca_bv = (const float*)d_in[17];
    const float* ca_wo = (const float*)d_in[18];
    const float* ca_bo = (const float*)d_in[19];
    const float* ff_w1 = (const float*)d_in[20];
    const float* ff_b1 = (const float*)d_in[21];
    const float* ff_w2 = (const float*)d_in[22];
    const float* ff_b2 = (const float*)d_in[23];
    const float* ln1_g = (const float*)d_in[24];
    const float* ln1_b = (const float*)d_in[25];
    const float* ln2_g = (const float*)d_in[26];
    const float* ln2_b = (const float*)d_in[27];
    const float* ln3_g = (const float*)d_in[28];
    const float* ln3_b = (const float*)d_in[29];

    float* out_tgt  = (float*)d_out;
    float* out_attn = (float*)d_out + (long)Mtok * Dm;

    __half *hA, *hE, *hQ, *hK, *hV, *hVT, *hT, *hX, *hFF;
    __half *hWqkv, *hWckv, *hWso, *hWcq, *hWco, *hW1, *hW2;
    float *Bqkv, *Bckv, *F0, *X1, *X2;
    cudaGetSymbolAddress((void**)&hA, g_hA);
    cudaGetSymbolAddress((void**)&hE, g_hE);
    cudaGetSymbolAddress((void**)&hQ, g_hQ);
    cudaGetSymbolAddress((void**)&hK, g_hK);
    cudaGetSymbolAddress((void**)&hV, g_hV);
    cudaGetSymbolAddress((void**)&hVT, g_hVT);
    cudaGetSymbolAddress((void**)&hT, g_hT);
    cudaGetSymbolAddress((void**)&hX, g_hX);
    cudaGetSymbolAddress((void**)&hFF, g_hFF);
    cudaGetSymbolAddress((void**)&hWqkv, g_hWqkv);
    cudaGetSymbolAddress((void**)&hWckv, g_hWckv);
    cudaGetSymbolAddress((void**)&hWso, g_hWso);
    cudaGetSymbolAddress((void**)&hWcq, g_hWcq);
    cudaGetSymbolAddress((void**)&hWco, g_hWco);
    cudaGetSymbolAddress((void**)&hW1, g_hW1);
    cudaGetSymbolAddress((void**)&hW2, g_hW2);
    cudaGetSymbolAddress((void**)&Bqkv, g_Bqkv);
    cudaGetSymbolAddress((void**)&Bckv, g_Bckv);
    cudaGetSymbolAddress((void**)&F0, g_F0);
    cudaGetSymbolAddress((void**)&X1, g_X1);
    cudaGetSymbolAddress((void**)&X2, g_X2);

    const int DDe = Dm * Dm;
    const int nbh = Bz * Hn;
    dim3 tgrid(Tq / 64, nbh);
    dim3 fgrid(Tq / 128, nbh);

    // ---- converts: one batched kernel (12 slices) + bias pack ----
    {
        CvtN p;
        int td = Mtok * Dm / 4;
        int wd = DDe / 4;
        p.s[0] = tgt;    p.d[0] = hA;              p.n4[0] = td;
        p.s[1] = enc;    p.d[1] = hE;              p.n4[1] = td;
        p.s[2] = sa_wq;  p.d[2] = hWqkv;           p.n4[2] = wd;
        p.s[3] = sa_wk;  p.d[3] = hWqkv + DDe;     p.n4[3] = wd;
        p.s[4] = sa_wv;  p.d[4] = hWqkv + 2 * DDe; p.n4[4] = wd;
        p.s[5] = sa_wo;  p.d[5] = hWso;            p.n4[5] = wd;
        p.s[6] = ca_wq;  p.d[6] = hWcq;            p.n4[6] = wd;
        p.s[7] = ca_wk;  p.d[7] = hWckv;           p.n4[7] = wd;
        p.s[8] = ca_wv;  p.d[8] = hWckv + DDe;     p.n4[8] = wd;
        p.s[9] = ca_wo;  p.d[9] = hWco;            p.n4[9] = wd;
        p.s[10] = ff_w1; p.d[10] = hW1;            p.n4[10] = td;
        p.s[11] = ff_w2; p.d[11] = hW2;            p.n4[11] = td;
        dim3 cgrid((td + 255) / 256, 12);
        f2hN<<<cgrid, 256>>>(p);
        pack_bias<<<20, 256>>>(sa_bq, sa_bk, sa_bv, ca_bk, ca_bv, Bqkv, Bckv);
    }

    // ---- self-attention ----
    gx<3, true>(hA, Dm, hWqkv, Dm, hQ, hK, hV, Dm, Mtok, 3 * Dm, Dm, Bqkv, 0);
    transpose_vh<<<tgrid, 256>>>(hV, hVT);
    flash_attn<0><<<fgrid, 256, FLASH_SMEM>>>(hQ, hK, hVT, hT, nullptr);
    gx<1, false>(hT, Dm, hWso, Dm, F0, nullptr, nullptr, Dm, Mtok, Dm, Dm, sa_bo, 0);
    add_ln<<<Mtok, 256>>>(F0, tgt, ln1_g, ln1_b, X1, hX);

    // ---- cross-attention (probs fused straight into d_out) ----
    gx<1, true>(hX, Dm, hWcq, Dm, hQ, nullptr, nullptr, Dm, Mtok, Dm, Dm, ca_bq, 0);
    gx<2, true>(hE, Dm, hWckv, Dm, hK, hV, nullptr, Dm, Mtok, 2 * Dm, Dm, Bckv, 0);
    transpose_vh<<<tgrid, 256>>>(hV, hVT);
    flash_attn<1><<<fgrid, 256, FLASH_SMEM>>>(hQ, hK, hVT, hT, out_attn);
    gx<1, false>(hT, Dm, hWco, Dm, F0, nullptr, nullptr, Dm, Mtok, Dm, Dm, ca_bo, 0);
    add_ln<<<Mtok, 256>>>(F0, X1, ln2_g, ln2_b, X2, hX);

    // ---- feed-forward ----
    gx<1, true>(hX, Dm, hW1, Dm, hFF, nullptr, nullptr, Fd, Mtok, Fd, Dm, ff_b1, 1);
    gx<1, false>(hFF, Fd, hW2, Fd, F0, nullptr, nullptr, Dm, Mtok, Dm, Fd, ff_b2, 0);
    add_ln<<<Mtok, 256>>>(F0, X2, ln3_g, ln3_b, out_tgt, nullptr);
}